// round 6
// baseline (speedup 1.0000x reference)
#include <cuda_runtime.h>

#define NN 131072
#define GG 4096
#define EE 1048576
#define SS 64
#define HH 128

// Scratch (no allocations allowed). 16B-aligned for float4 / v4-red access.
__device__ __align__(16) float  g_w_src[2][SS];     // W @ att_src per branch
__device__ __align__(16) float  g_a_dstv[2][GG];    // a_dst at self node of each graph
__device__ __align__(16) float  g_acc[2][GG * SS];  // sum of p * x[src] per graph (S-space)
__device__ __align__(16) float  g_denom[2][GG];     // sum of p per graph
__device__ __align__(16) float2 g_Wt2[HH * SS];     // Wt2[c*64+s] = (Wup[s][c], Wdn[s][c])

// =========================================================================
// K1: zero accumulators + w_src/w_dst prep + Wt2 transpose + a_dst(self)
// 128 blocks x 256 threads. w_dst is computed redundantly per block into
// smem (removes cross-block dependency); block 0 publishes w_src globally.
__global__ void setup_kernel(const float* __restrict__ upW,
                             const float* __restrict__ upAs,
                             const float* __restrict__ upAd,
                             const float* __restrict__ dnW,
                             const float* __restrict__ dnAs,
                             const float* __restrict__ dnAd,
                             const float* __restrict__ up_x,
                             const float* __restrict__ dn_x) {
    __shared__ float wdst_sh[2][SS];
    int t = threadIdx.x, b = blockIdx.x;

    // --- zero g_acc (131072 float4 over 128 blocks -> 1024/block) + g_denom
    float4* accv = (float4*)g_acc;
    int base = b * 1024;
    const float4 z4 = make_float4(0.f, 0.f, 0.f, 0.f);
#pragma unroll
    for (int i = 0; i < 4; i++) accv[base + i * 256 + t] = z4;
    float4* denv = (float4*)g_denom;                 // 2048 float4 total
    if (t < 16) denv[b * 16 + t] = z4;

    // --- w_src / w_dst (one pass over h computes both dots)
    if (t < 128) {
        int br = t >> 6, s = t & 63;
        const float* W   = br ? dnW  : upW;
        const float* as_ = br ? dnAs : upAs;
        const float* ad_ = br ? dnAd : upAd;
        float ssum = 0.f, dsum = 0.f;
#pragma unroll 8
        for (int h = 0; h < HH; h++) {
            float w = W[s * HH + h];
            ssum += w * as_[h];
            dsum += w * ad_[h];
        }
        wdst_sh[br][s] = dsum;
        if (b == 0) g_w_src[br][s] = ssum;
    }

    // --- Wt2 build (blocks 0..15, 512 float2 each)
    if (b < 16) {
        int i0 = b * 512 + t * 2;
#pragma unroll
        for (int j = 0; j < 2; j++) {
            int i = i0 + j;
            int c = i >> 6, s = i & 63;
            g_Wt2[i] = make_float2(upW[s * HH + c], dnW[s * HH + c]);
        }
    }
    __syncthreads();

    // --- a_dst for self node 32g+31 of every graph: 64 warp-tasks per block
    int warpId = t >> 5, lane = t & 31;
    float2 wv0 = *(const float2*)&wdst_sh[0][lane * 2];
    float2 wv1 = *(const float2*)&wdst_sh[1][lane * 2];
#pragma unroll
    for (int it = 0; it < 8; it++) {
        int id = b * 64 + warpId * 8 + it;           // 0..8191
        int br = id & 1, g = id >> 1;
        const float* x = br ? dn_x : up_x;
        float2 wv = br ? wv1 : wv0;
        float2 xv = *(const float2*)(x + (size_t)(g * 32 + 31) * SS + lane * 2);
        float s = xv.x * wv.x + xv.y * wv.y;
#pragma unroll
        for (int o = 16; o; o >>= 1) s += __shfl_xor_sync(0xffffffffu, s, o);
        if (lane == 0) g_a_dstv[br][g] = s;
    }
}

// =========================================================================
// K2: single edge pass. edge_index is int32. Only edges with dst%32==31
// matter (~1/32). Eager int4 loads: 4 src + 4 dst per thread (same DRAM
// cost as lazy sparse src reads — every 128B line holds ~1 relevant — but
// coalesced and MLP=2). For relevant edges:
//   p = exp(leaky_relu(x[src].w_src + a_dst[g]))   (no max-shift needed)
//   acc[g][:] += p * x[src][:],  denom[g] += p
// Warp-cooperative: ballot-compacted; 16 lanes cover the 64-float row as
// float4s (upper half mirrors); scatter via red.global.add.v4.f32 (L2-res).
__global__ void edge_kernel(const int* __restrict__ up_ei,
                            const int* __restrict__ dn_ei,
                            const float* __restrict__ up_x,
                            const float* __restrict__ dn_x) {
    int branch = blockIdx.y;
    const int*   ei = branch ? dn_ei : up_ei;
    const float* x  = branch ? dn_x  : up_x;
    float* acc   = g_acc[branch];
    float* denom = g_denom[branch];
    const float* adst = g_a_dstv[branch];
    int lane = threadIdx.x & 31;

    float4 wv = *(const float4*)&g_w_src[branch][(lane & 15) * 4];

    int e0 = (blockIdx.x * blockDim.x + threadIdx.x) * 4;
    int4 d4 = *(const int4*)(ei + EE + e0);   // dst stream
    int4 s4 = *(const int4*)(ei + e0);        // src stream (independent load)
    int ds[4] = {d4.x, d4.y, d4.z, d4.w};
    int ss[4] = {s4.x, s4.y, s4.z, s4.w};

#pragma unroll
    for (int k = 0; k < 4; k++) {
        bool rel = (ds[k] & 31) == 31;
        int gph = ds[k] >> 5;
        int src = ss[k];
        unsigned m = __ballot_sync(0xffffffffu, rel);
        while (m) {
            int l = __ffs(m) - 1;
            m &= m - 1;
            int s2 = __shfl_sync(0xffffffffu, src, l);
            int g2 = __shfl_sync(0xffffffffu, gph, l);
            float ad = adst[g2];                                    // L1/L2 hit
            float4 v = *(const float4*)(x + (size_t)s2 * SS + (lane & 15) * 4);
            float part = v.x * wv.x + v.y * wv.y + v.z * wv.z + v.w * wv.w;
#pragma unroll
            for (int o = 8; o; o >>= 1)
                part += __shfl_xor_sync(0xffffffffu, part, o);      // 16-group sum
            float ev = part + ad;
            ev = ev > 0.f ? ev : 0.2f * ev;                         // leaky_relu
            float p = __expf(ev);
            if (lane < 16) {
                float* addr = acc + g2 * SS + lane * 4;
                asm volatile("red.global.add.v4.f32 [%0], {%1,%2,%3,%4};"
                             :: "l"(addr), "f"(v.x * p), "f"(v.y * p),
                                "f"(v.z * p), "f"(v.w * p)
                             : "memory");
            } else if (lane == 16) {
                atomicAdd(denom + g2, p);
            }
        }
    }
}

// =========================================================================
// K3: epilogue, warp-per-graph (512 blocks x 256 threads = 4096 warps).
//   v_b = acc_b[g]/(denom_b[g]+1e-16); h_b = sigmoid(v_b @ W_b + bias_b)
//   out[g] = (h_up . h_dn . mlpW) + mlpb
// Up/down packed as f32x2 pairs; fma.rn.f32x2 (FFMA2, PTX-only). Each warp
// writes + reads only its own vsh row -> __syncwarp, no block barriers.
__global__ void final_kernel(const float* __restrict__ upB,
                             const float* __restrict__ dnB,
                             const float* __restrict__ mlpW,
                             const float* __restrict__ mlpB,
                             float* __restrict__ out) {
    __shared__ __align__(16) float2 vsh[8][SS];
    int t = threadIdx.x, w = t >> 5, lane = t & 31;
    int g = blockIdx.x * 8 + w;

    {   // load v for this warp's graph: lane covers s = 2*lane, 2*lane+1
        float invu = __fdividef(1.f, g_denom[0][g] + 1e-16f);
        float invd = __fdividef(1.f, g_denom[1][g] + 1e-16f);
        int s0 = lane * 2;
        float2 au = *(const float2*)&g_acc[0][g * SS + s0];
        float2 ad = *(const float2*)&g_acc[1][g * SS + s0];
        vsh[w][s0]     = make_float2(au.x * invu, ad.x * invd);
        vsh[w][s0 + 1] = make_float2(au.y * invu, ad.y * invd);
    }
    __syncwarp();

    unsigned long long acc2[4] = {0ull, 0ull, 0ull, 0ull};
#pragma unroll 4
    for (int s = 0; s < SS; s += 2) {
        float4 vv = *(const float4*)&vsh[w][s];     // (u_s, d_s, u_s1, d_s1)
        unsigned long long v0, v1;
        asm("mov.b64 %0, {%1,%2};" : "=l"(v0) : "f"(vv.x), "f"(vv.y));
        asm("mov.b64 %0, {%1,%2};" : "=l"(v1) : "f"(vv.z), "f"(vv.w));
#pragma unroll
        for (int j = 0; j < 4; j++) {
            int c = lane + 32 * j;
            float4 ww = *(const float4*)&g_Wt2[c * SS + s];
            unsigned long long w0, w1;
            asm("mov.b64 %0, {%1,%2};" : "=l"(w0) : "f"(ww.x), "f"(ww.y));
            asm("mov.b64 %0, {%1,%2};" : "=l"(w1) : "f"(ww.z), "f"(ww.w));
            asm("fma.rn.f32x2 %0, %1, %2, %0;" : "+l"(acc2[j]) : "l"(v0), "l"(w0));
            asm("fma.rn.f32x2 %0, %1, %2, %0;" : "+l"(acc2[j]) : "l"(v1), "l"(w1));
        }
    }

    float pr = 0.f;
#pragma unroll
    for (int j = 0; j < 4; j++) {
        int c = lane + 32 * j;
        float su, sd;
        asm("mov.b64 {%0,%1}, %2;" : "=f"(su), "=f"(sd) : "l"(acc2[j]));
        float hu = 1.f / (1.f + __expf(-(su + upB[c])));
        float hd = 1.f / (1.f + __expf(-(sd + dnB[c])));
        pr += hu * hd * mlpW[c];
    }
#pragma unroll
    for (int o = 16; o; o >>= 1) pr += __shfl_xor_sync(0xffffffffu, pr, o);
    if (lane == 0) out[g] = pr + mlpB[0];
}

// =========================================================================
extern "C" void kernel_launch(void* const* d_in, const int* in_sizes, int n_in,
                              void* d_out, int out_size) {
    const float* up_x  = (const float*)d_in[0];
    const int*   up_ei = (const int*)d_in[1];
    const float* dn_x  = (const float*)d_in[3];
    const int*   dn_ei = (const int*)d_in[4];
    const float* upW   = (const float*)d_in[6];
    const float* upAs  = (const float*)d_in[7];
    const float* upAd  = (const float*)d_in[8];
    const float* upB   = (const float*)d_in[9];
    const float* dnW   = (const float*)d_in[10];
    const float* dnAs  = (const float*)d_in[11];
    const float* dnAd  = (const float*)d_in[12];
    const float* dnB   = (const float*)d_in[13];
    const float* mlpW  = (const float*)d_in[14];
    const float* mlpB  = (const float*)d_in[15];
    float* out = (float*)d_out;

    setup_kernel<<<128, 256>>>(upW, upAs, upAd, dnW, dnAs, dnAd, up_x, dn_x);
    dim3 egrid(EE / 4 / 256, 2);
    edge_kernel<<<egrid, 256>>>(up_ei, dn_ei, up_x, dn_x);
    final_kernel<<<GG / 8, 256>>>(upB, dnB, mlpW, mlpB, out);
}

// round 8
// speedup vs baseline: 1.1388x; 1.1388x over previous
#include <cuda_runtime.h>

#define NN 131072
#define GG 4096
#define EE 1048576
#define SS 64
#define HH 128

// Scratch (no allocations allowed). 16B-aligned for float4 / v4-red access.
__device__ __align__(16) float  g_w_src[2][SS];     // W @ att_src per branch
__device__ __align__(16) float  g_w_dst[2][SS];     // W @ att_dst per branch
__device__ __align__(16) float  g_a_dstv[2][GG];    // a_dst at self node of each graph
__device__ __align__(16) float  g_acc[2][GG * SS];  // sum of p * x[src] per graph (S-space)
__device__ __align__(16) float  g_denom[2][GG];     // sum of p per graph
__device__ __align__(16) float2 g_Wt2[HH * SS];     // Wt2[c*64+s] = (Wup[s][c], Wdn[s][c])

// =========================================================================
// K1 init, grid 152 x 256:
//   blocks [0,128):   zero g_acc / g_denom
//   blocks [128,144): build Wt2 packed-transpose
//   blocks [144,152): 256 prep dots (w_src/w_dst, both branches), one dot
//                     per warp-task, lane-strided over h + butterfly reduce
__global__ void init_kernel(const float* __restrict__ upW,
                            const float* __restrict__ upAs,
                            const float* __restrict__ upAd,
                            const float* __restrict__ dnW,
                            const float* __restrict__ dnAs,
                            const float* __restrict__ dnAd) {
    int t = threadIdx.x, b = blockIdx.x;
    if (b < 128) {
        float4* accv = (float4*)g_acc;               // 131072 float4 total
        const float4 z4 = make_float4(0.f, 0.f, 0.f, 0.f);
        int base = b * 1024;
#pragma unroll
        for (int i = 0; i < 4; i++) accv[base + i * 256 + t] = z4;
        if (t < 16) ((float4*)g_denom)[b * 16 + t] = z4;   // 2048 float4
    } else if (b < 144) {
        int i0 = (b - 128) * 512 + t * 2;            // 8192 float2 total
#pragma unroll
        for (int j = 0; j < 2; j++) {
            int i = i0 + j, c = i >> 6, s = i & 63;
            g_Wt2[i] = make_float2(upW[s * HH + c], dnW[s * HH + c]);
        }
    } else {
        // 8 blocks x 8 warps = 64 warps, 4 dots each -> 256 dots
        int warpId = t >> 5, lane = t & 31;
#pragma unroll
        for (int i = 0; i < 4; i++) {
            int dotId = (b - 144) * 32 + warpId * 4 + i;   // 0..255
            int vec = dotId >> 6, s = dotId & 63;          // vec: 0 us,1 ud,2 ds,3 dd
            const float* W = (vec < 2) ? upW : dnW;
            const float* a = (vec == 0) ? upAs : (vec == 1) ? upAd
                            : (vec == 2) ? dnAs : dnAd;
            float sum = 0.f;
#pragma unroll
            for (int j = 0; j < 4; j++) {
                int h = lane + 32 * j;
                sum += W[s * HH + h] * a[h];
            }
#pragma unroll
            for (int o = 16; o; o >>= 1) sum += __shfl_xor_sync(0xffffffffu, sum, o);
            if (lane == 0) {
                float* dstp = (vec == 0) ? g_w_src[0] : (vec == 1) ? g_w_dst[0]
                             : (vec == 2) ? g_w_src[1] : g_w_dst[1];
                dstp[s] = sum;
            }
        }
    }
}

// =========================================================================
// K2: a_dst at the self node (32g+31) of every graph, both branches.
// One warp per (branch, graph): 8192 warp-tasks.
__global__ void dstval_kernel(const float* __restrict__ up_x,
                              const float* __restrict__ dn_x) {
    int wid = (blockIdx.x * blockDim.x + threadIdx.x) >> 5;
    int lane = threadIdx.x & 31;
    int branch = wid & 1, g = wid >> 1;
    const float* x = branch ? dn_x : up_x;
    float2 xv = *(const float2*)(x + (size_t)(g * 32 + 31) * SS + lane * 2);
    float2 wv = *(const float2*)(&g_w_dst[branch][lane * 2]);
    float s = xv.x * wv.x + xv.y * wv.y;
#pragma unroll
    for (int o = 16; o; o >>= 1) s += __shfl_xor_sync(0xffffffffu, s, o);
    if (lane == 0) g_a_dstv[branch][g] = s;
}

// =========================================================================
// K3: edge pass (R4-proven memory pattern: 1 edge/thread, coalesced dst
// stream, lazy src load). Only dst%32==31 edges matter (~1/32). NEW: each
// ballot round retires TWO relevant edges — lanes 0-15 process edge A,
// lanes 16-31 process edge B (upper half previously just mirrored).
//   p = exp(leaky_relu(x[src].w_src + a_dst[g]))   (no max-shift needed)
//   acc[g][:] += p * x[src][:],  denom[g] += p     (red.global.add.v4.f32)
__global__ void edge_kernel(const int* __restrict__ up_ei,
                            const int* __restrict__ dn_ei,
                            const float* __restrict__ up_x,
                            const float* __restrict__ dn_x) {
    int branch = blockIdx.y;
    const int*   ei = branch ? dn_ei : up_ei;
    const float* x  = branch ? dn_x  : up_x;
    float* acc   = g_acc[branch];
    float* denom = g_denom[branch];
    const float* adst = g_a_dstv[branch];
    int lane = threadIdx.x & 31;

    float4 wv = *(const float4*)&g_w_src[branch][(lane & 15) * 4];

    int e = blockIdx.x * blockDim.x + threadIdx.x;
    int d = ei[EE + e];                       // coalesced dst stream
    bool rel = (d & 31) == 31;
    int gph = d >> 5;
    int src = rel ? ei[e] : 0;                // lazy src load (~1/32 lanes)

    unsigned m = __ballot_sync(0xffffffffu, rel);
    while (m) {
        int lA = __ffs(m) - 1;  m &= m - 1;
        int lB = m ? (__ffs(m) - 1) : lA;
        bool two = (lB != lA);
        if (two) m &= m - 1;

        int myl = (lane < 16) ? lA : lB;
        int s2 = __shfl_sync(0xffffffffu, src, myl);
        int g2 = __shfl_sync(0xffffffffu, gph, myl);
        float ad = adst[g2];                                     // L2-resident
        float4 v = *(const float4*)(x + (size_t)s2 * SS + (lane & 15) * 4);
        float part = v.x * wv.x + v.y * wv.y + v.z * wv.z + v.w * wv.w;
#pragma unroll
        for (int o = 8; o; o >>= 1)
            part += __shfl_xor_sync(0xffffffffu, part, o);       // 16-group sum
        float ev = part + ad;
        ev = ev > 0.f ? ev : 0.2f * ev;                          // leaky_relu 0.2
        float p = __expf(ev);
        if (lane < 16 || two) {
            float* addr = acc + g2 * SS + (lane & 15) * 4;
            asm volatile("red.global.add.v4.f32 [%0], {%1,%2,%3,%4};"
                         :: "l"(addr), "f"(v.x * p), "f"(v.y * p),
                            "f"(v.z * p), "f"(v.w * p)
                         : "memory");
        }
        if (lane == 0) atomicAdd(denom + g2, p);
        if (lane == 16 && two) atomicAdd(denom + g2, p);
    }
}

// =========================================================================
// K4: epilogue, warp-per-graph (512 blocks x 256 threads = 4096 warps).
//   v_b = acc_b[g]/(denom_b[g]+1e-16); h_b = sigmoid(v_b @ W_b + bias_b)
//   out[g] = (h_up . h_dn . mlpW) + mlpb
// Up/down packed as f32x2 pairs; fma.rn.f32x2 (FFMA2, PTX-only). Each warp
// touches only its own vsh row -> __syncwarp, no block barriers.
__global__ void final_kernel(const float* __restrict__ upB,
                             const float* __restrict__ dnB,
                             const float* __restrict__ mlpW,
                             const float* __restrict__ mlpB,
                             float* __restrict__ out) {
    __shared__ __align__(16) float2 vsh[8][SS];
    int t = threadIdx.x, w = t >> 5, lane = t & 31;
    int g = blockIdx.x * 8 + w;

    {   // v for this warp's graph: lane covers s = 2*lane, 2*lane+1
        float invu = __fdividef(1.f, g_denom[0][g] + 1e-16f);
        float invd = __fdividef(1.f, g_denom[1][g] + 1e-16f);
        int s0 = lane * 2;
        float2 au = *(const float2*)&g_acc[0][g * SS + s0];
        float2 ad = *(const float2*)&g_acc[1][g * SS + s0];
        vsh[w][s0]     = make_float2(au.x * invu, ad.x * invd);
        vsh[w][s0 + 1] = make_float2(au.y * invu, ad.y * invd);
    }
    __syncwarp();

    unsigned long long acc2[4] = {0ull, 0ull, 0ull, 0ull};
#pragma unroll 4
    for (int s = 0; s < SS; s += 2) {
        float4 vv = *(const float4*)&vsh[w][s];     // (u_s, d_s, u_s1, d_s1)
        unsigned long long v0, v1;
        asm("mov.b64 %0, {%1,%2};" : "=l"(v0) : "f"(vv.x), "f"(vv.y));
        asm("mov.b64 %0, {%1,%2};" : "=l"(v1) : "f"(vv.z), "f"(vv.w));
#pragma unroll
        for (int j = 0; j < 4; j++) {
            int c = lane + 32 * j;
            float4 ww = *(const float4*)&g_Wt2[c * SS + s];
            unsigned long long w0, w1;
            asm("mov.b64 %0, {%1,%2};" : "=l"(w0) : "f"(ww.x), "f"(ww.y));
            asm("mov.b64 %0, {%1,%2};" : "=l"(w1) : "f"(ww.z), "f"(ww.w));
            asm("fma.rn.f32x2 %0, %1, %2, %0;" : "+l"(acc2[j]) : "l"(v0), "l"(w0));
            asm("fma.rn.f32x2 %0, %1, %2, %0;" : "+l"(acc2[j]) : "l"(v1), "l"(w1));
        }
    }

    float pr = 0.f;
#pragma unroll
    for (int j = 0; j < 4; j++) {
        int c = lane + 32 * j;
        float su, sd;
        asm("mov.b64 {%0,%1}, %2;" : "=f"(su), "=f"(sd) : "l"(acc2[j]));
        float hu = 1.f / (1.f + __expf(-(su + upB[c])));
        float hd = 1.f / (1.f + __expf(-(sd + dnB[c])));
        pr += hu * hd * mlpW[c];
    }
#pragma unroll
    for (int o = 16; o; o >>= 1) pr += __shfl_xor_sync(0xffffffffu, pr, o);
    if (lane == 0) out[g] = pr + mlpB[0];
}

// =========================================================================
extern "C" void kernel_launch(void* const* d_in, const int* in_sizes, int n_in,
                              void* d_out, int out_size) {
    const float* up_x  = (const float*)d_in[0];
    const int*   up_ei = (const int*)d_in[1];
    const float* dn_x  = (const float*)d_in[3];
    const int*   dn_ei = (const int*)d_in[4];
    const float* upW   = (const float*)d_in[6];
    const float* upAs  = (const float*)d_in[7];
    const float* upAd  = (const float*)d_in[8];
    const float* upB   = (const float*)d_in[9];
    const float* dnW   = (const float*)d_in[10];
    const float* dnAs  = (const float*)d_in[11];
    const float* dnAd  = (const float*)d_in[12];
    const float* dnB   = (const float*)d_in[13];
    const float* mlpW  = (const float*)d_in[14];
    const float* mlpB  = (const float*)d_in[15];
    float* out = (float*)d_out;

    init_kernel<<<152, 256>>>(upW, upAs, upAd, dnW, dnAs, dnAd);
    dstval_kernel<<<1024, 256>>>(up_x, dn_x);
    dim3 egrid(EE / 256, 2);
    edge_kernel<<<egrid, 256>>>(up_ei, dn_ei, up_x, dn_x);
    final_kernel<<<GG / 8, 256>>>(upB, dnB, mlpW, mlpB, out);
}

// round 13
// speedup vs baseline: 2.2336x; 1.9614x over previous
#include <cuda_runtime.h>

#define NN 131072
#define GG 4096
#define EE 1048576
#define SS 64
#define HH 128

typedef unsigned long long ull;

// Scratch (no allocations allowed). 16B-aligned for float4 / v4-red access.
__device__ __align__(16) float  g_w_src[2][SS];     // W @ att_src per branch
__device__ __align__(16) float  g_w_dst[2][SS];     // W @ att_dst per branch
__device__ __align__(16) float  g_a_dstv[2][GG];    // a_dst at self node of each graph
__device__ __align__(16) float  g_acc[2][GG * SS];  // sum of p * x[src] per graph (S-space)
__device__ __align__(16) float  g_denom[2][GG];     // sum of p per graph
// Packed transpose, S-MAJOR: Wt2[s*128 + c] = (Wup[s][c], Wdn[s][c]).
// Fixed s => lanes read consecutive float2 (8B lane stride, coalesced).
__device__ __align__(16) float2 g_Wt2[SS * HH];

// =========================================================================
// K1 init, grid 152 x 256:
//   blocks [0,128):   zero g_acc / g_denom
//   blocks [128,144): build Wt2 packed interleave (s-major, coalesced r+w)
//   blocks [144,152): 256 prep dots (w_src/w_dst, both branches), one dot
//                     per warp-task, lane-strided over h + butterfly reduce
__global__ void init_kernel(const float* __restrict__ upW,
                            const float* __restrict__ upAs,
                            const float* __restrict__ upAd,
                            const float* __restrict__ dnW,
                            const float* __restrict__ dnAs,
                            const float* __restrict__ dnAd) {
    int t = threadIdx.x, b = blockIdx.x;
    if (b < 128) {
        float4* accv = (float4*)g_acc;               // 131072 float4 total
        const float4 z4 = make_float4(0.f, 0.f, 0.f, 0.f);
        int base = b * 1024;
#pragma unroll
        for (int i = 0; i < 4; i++) accv[base + i * 256 + t] = z4;
        if (t < 16) ((float4*)g_denom)[b * 16 + t] = z4;   // 2048 float4
    } else if (b < 144) {
        int i0 = (b - 128) * 512 + t * 2;            // 8192 float2 total
#pragma unroll
        for (int j = 0; j < 2; j++) {
            int i = i0 + j;                          // i = s*128 + c
            g_Wt2[i] = make_float2(upW[i], dnW[i]);  // same linear index!
        }
    } else {
        // 8 blocks x 8 warps = 64 warps, 4 dots each -> 256 dots
        int warpId = t >> 5, lane = t & 31;
#pragma unroll
        for (int i = 0; i < 4; i++) {
            int dotId = (b - 144) * 32 + warpId * 4 + i;   // 0..255
            int vec = dotId >> 6, s = dotId & 63;          // vec: 0 us,1 ud,2 ds,3 dd
            const float* W = (vec < 2) ? upW : dnW;
            const float* a = (vec == 0) ? upAs : (vec == 1) ? upAd
                            : (vec == 2) ? dnAs : dnAd;
            float sum = 0.f;
#pragma unroll
            for (int j = 0; j < 4; j++) {
                int h = lane + 32 * j;
                sum += W[s * HH + h] * a[h];
            }
#pragma unroll
            for (int o = 16; o; o >>= 1) sum += __shfl_xor_sync(0xffffffffu, sum, o);
            if (lane == 0) {
                float* dstp = (vec == 0) ? g_w_src[0] : (vec == 1) ? g_w_dst[0]
                             : (vec == 2) ? g_w_src[1] : g_w_dst[1];
                dstp[s] = sum;
            }
        }
    }
}

// =========================================================================
// K2: a_dst at the self node (32g+31) of every graph, both branches.
// One warp per (branch, graph): 8192 warp-tasks.
__global__ void dstval_kernel(const float* __restrict__ up_x,
                              const float* __restrict__ dn_x) {
    int wid = (blockIdx.x * blockDim.x + threadIdx.x) >> 5;
    int lane = threadIdx.x & 31;
    int branch = wid & 1, g = wid >> 1;
    const float* x = branch ? dn_x : up_x;
    float2 xv = *(const float2*)(x + (size_t)(g * 32 + 31) * SS + lane * 2);
    float2 wv = *(const float2*)(&g_w_dst[branch][lane * 2]);
    float s = xv.x * wv.x + xv.y * wv.y;
#pragma unroll
    for (int o = 16; o; o >>= 1) s += __shfl_xor_sync(0xffffffffu, s, o);
    if (lane == 0) g_a_dstv[branch][g] = s;
}

// =========================================================================
// K3: edge pass (unchanged from R8 — passing). 1 edge/thread, coalesced dst
// stream, lazy src load; dual-edge ballot rounds (lanes 0-15 edge A, 16-31
// edge B).  p = exp(leaky_relu(x[src].w_src + a_dst[g]));
//   acc[g][:] += p * x[src][:],  denom[g] += p     (red.global.add.v4.f32)
__global__ void edge_kernel(const int* __restrict__ up_ei,
                            const int* __restrict__ dn_ei,
                            const float* __restrict__ up_x,
                            const float* __restrict__ dn_x) {
    int branch = blockIdx.y;
    const int*   ei = branch ? dn_ei : up_ei;
    const float* x  = branch ? dn_x  : up_x;
    float* acc   = g_acc[branch];
    float* denom = g_denom[branch];
    const float* adst = g_a_dstv[branch];
    int lane = threadIdx.x & 31;

    float4 wv = *(const float4*)&g_w_src[branch][(lane & 15) * 4];

    int e = blockIdx.x * blockDim.x + threadIdx.x;
    int d = ei[EE + e];                       // coalesced dst stream
    bool rel = (d & 31) == 31;
    int gph = d >> 5;
    int src = rel ? ei[e] : 0;                // lazy src load (~1/32 lanes)

    unsigned m = __ballot_sync(0xffffffffu, rel);
    while (m) {
        int lA = __ffs(m) - 1;  m &= m - 1;
        int lB = m ? (__ffs(m) - 1) : lA;
        bool two = (lB != lA);
        if (two) m &= m - 1;

        int myl = (lane < 16) ? lA : lB;
        int s2 = __shfl_sync(0xffffffffu, src, myl);
        int g2 = __shfl_sync(0xffffffffu, gph, myl);
        float ad = adst[g2];                                     // L2-resident
        float4 v = *(const float4*)(x + (size_t)s2 * SS + (lane & 15) * 4);
        float part = v.x * wv.x + v.y * wv.y + v.z * wv.z + v.w * wv.w;
#pragma unroll
        for (int o = 8; o; o >>= 1)
            part += __shfl_xor_sync(0xffffffffu, part, o);       // 16-group sum
        float ev = part + ad;
        ev = ev > 0.f ? ev : 0.2f * ev;                          // leaky_relu 0.2
        float p = __expf(ev);
        if (lane < 16 || two) {
            float* addr = acc + g2 * SS + (lane & 15) * 4;
            asm volatile("red.global.add.v4.f32 [%0], {%1,%2,%3,%4};"
                         :: "l"(addr), "f"(v.x * p), "f"(v.y * p),
                            "f"(v.z * p), "f"(v.w * p)
                         : "memory");
        }
        if (lane == 0) atomicAdd(denom + g2, p);
        if (lane == 16 && two) atomicAdd(denom + g2, p);
    }
}

// =========================================================================
// K4: epilogue, warp-per-graph (512 blocks x 256 threads = 4096 warps).
//   v_b = acc_b[g]/(denom_b[g]+1e-16); h_b = sigmoid(v_b @ W_b + bias_b)
//   out[g] = (h_up . h_dn . mlpW) + mlpb
// S-major Wt2: per s, lane reads one coalesced 8B pair per j (2 wavefronts
// per warp-load vs 32 before). Pairs live directly in 64-bit regs; FFMA2
// (fma.rn.f32x2, PTX-only) with 4 independent accumulator chains.
__global__ void final_kernel(const float* __restrict__ upB,
                             const float* __restrict__ dnB,
                             const float* __restrict__ mlpW,
                             const float* __restrict__ mlpB,
                             float* __restrict__ out) {
    __shared__ __align__(16) ull vsh[8][SS];
    int t = threadIdx.x, w = t >> 5, lane = t & 31;
    int g = blockIdx.x * 8 + w;

    {   // v for this warp's graph: lane covers s = 2*lane, 2*lane+1
        float invu = __fdividef(1.f, g_denom[0][g] + 1e-16f);
        float invd = __fdividef(1.f, g_denom[1][g] + 1e-16f);
        int s0 = lane * 2;
        float2 au = *(const float2*)&g_acc[0][g * SS + s0];
        float2 ad = *(const float2*)&g_acc[1][g * SS + s0];
        ull p0, p1;
        asm("mov.b64 %0, {%1,%2};" : "=l"(p0) : "f"(au.x * invu), "f"(ad.x * invd));
        asm("mov.b64 %0, {%1,%2};" : "=l"(p1) : "f"(au.y * invu), "f"(ad.y * invd));
        vsh[w][s0]     = p0;
        vsh[w][s0 + 1] = p1;
    }
    __syncwarp();

    ull acc2[4] = {0ull, 0ull, 0ull, 0ull};
#pragma unroll 8
    for (int s = 0; s < SS; s++) {
        ull v = vsh[w][s];                               // LDS.64 broadcast
        const ull* wrow = (const ull*)&g_Wt2[s * HH];    // coalesced row
#pragma unroll
        for (int j = 0; j < 4; j++) {
            ull ww = wrow[lane + 32 * j];                // LDG.64, L1-resident
            asm("fma.rn.f32x2 %0, %1, %2, %0;" : "+l"(acc2[j]) : "l"(v), "l"(ww));
        }
    }

    float pr = 0.f;
#pragma unroll
    for (int j = 0; j < 4; j++) {
        int c = lane + 32 * j;
        float su, sd;
        asm("mov.b64 {%0,%1}, %2;" : "=f"(su), "=f"(sd) : "l"(acc2[j]));
        float hu = 1.f / (1.f + __expf(-(su + upB[c])));
        float hd = 1.f / (1.f + __expf(-(sd + dnB[c])));
        pr += hu * hd * mlpW[c];
    }
#pragma unroll
    for (int o = 16; o; o >>= 1) pr += __shfl_xor_sync(0xffffffffu, pr, o);
    if (lane == 0) out[g] = pr + mlpB[0];
}

// =========================================================================
extern "C" void kernel_launch(void* const* d_in, const int* in_sizes, int n_in,
                              void* d_out, int out_size) {
    const float* up_x  = (const float*)d_in[0];
    const int*   up_ei = (const int*)d_in[1];
    const float* dn_x  = (const float*)d_in[3];
    const int*   dn_ei = (const int*)d_in[4];
    const float* upW   = (const float*)d_in[6];
    const float* upAs  = (const float*)d_in[7];
    const float* upAd  = (const float*)d_in[8];
    const float* upB   = (const float*)d_in[9];
    const float* dnW   = (const float*)d_in[10];
    const float* dnAs  = (const float*)d_in[11];
    const float* dnAd  = (const float*)d_in[12];
    const float* dnB   = (const float*)d_in[13];
    const float* mlpW  = (const float*)d_in[14];
    const float* mlpB  = (const float*)d_in[15];
    float* out = (float*)d_out;

    init_kernel<<<152, 256>>>(upW, upAs, upAd, dnW, dnAs, dnAd);
    dstval_kernel<<<1024, 256>>>(up_x, dn_x);
    dim3 egrid(EE / 256, 2);
    edge_kernel<<<egrid, 256>>>(up_ei, dn_ei, up_x, dn_x);
    final_kernel<<<GG / 8, 256>>>(upB, dnB, mlpW, mlpB, out);
}

// round 15
// speedup vs baseline: 3.1477x; 1.4092x over previous
#include <cuda_runtime.h>

#define NN 131072
#define GG 4096
#define EE 1048576
#define SS 64
#define HH 128

typedef unsigned long long ull;

// Scratch (no allocations allowed). 16B-aligned for float4 / v4-red access.
__device__ __align__(16) float  g_w_src[2][SS];     // W @ att_src per branch
__device__ __align__(16) float  g_w_dst[2][SS];     // W @ att_dst per branch
__device__ __align__(16) float  g_a_dstv[2][GG];    // a_dst at self node of each graph
__device__ __align__(16) float  g_acc[2][GG * SS];  // sum of p * x[src] per graph (S-space)
__device__ __align__(16) float  g_denom[2][GG];     // sum of p per graph
// Packed transpose, S-MAJOR: Wt2[s*128 + c] = (Wup[s][c], Wdn[s][c]).
__device__ __align__(16) float2 g_Wt2[SS * HH];

// =========================================================================
// K1 init, grid 152 x 256 (unchanged, proven):
__global__ void init_kernel(const float* __restrict__ upW,
                            const float* __restrict__ upAs,
                            const float* __restrict__ upAd,
                            const float* __restrict__ dnW,
                            const float* __restrict__ dnAs,
                            const float* __restrict__ dnAd) {
    int t = threadIdx.x, b = blockIdx.x;
    if (b < 128) {
        float4* accv = (float4*)g_acc;               // 131072 float4 total
        const float4 z4 = make_float4(0.f, 0.f, 0.f, 0.f);
        int base = b * 1024;
#pragma unroll
        for (int i = 0; i < 4; i++) accv[base + i * 256 + t] = z4;
        if (t < 16) ((float4*)g_denom)[b * 16 + t] = z4;   // 2048 float4
    } else if (b < 144) {
        int i0 = (b - 128) * 512 + t * 2;            // 8192 float2 total
#pragma unroll
        for (int j = 0; j < 2; j++) {
            int i = i0 + j;                          // i = s*128 + c
            g_Wt2[i] = make_float2(upW[i], dnW[i]);  // same linear index
        }
    } else {
        // 8 blocks x 8 warps = 64 warps, 4 dots each -> 256 dots
        int warpId = t >> 5, lane = t & 31;
#pragma unroll
        for (int i = 0; i < 4; i++) {
            int dotId = (b - 144) * 32 + warpId * 4 + i;   // 0..255
            int vec = dotId >> 6, s = dotId & 63;          // 0 us,1 ud,2 ds,3 dd
            const float* W = (vec < 2) ? upW : dnW;
            const float* a = (vec == 0) ? upAs : (vec == 1) ? upAd
                            : (vec == 2) ? dnAs : dnAd;
            float sum = 0.f;
#pragma unroll
            for (int j = 0; j < 4; j++) {
                int h = lane + 32 * j;
                sum += W[s * HH + h] * a[h];
            }
#pragma unroll
            for (int o = 16; o; o >>= 1) sum += __shfl_xor_sync(0xffffffffu, sum, o);
            if (lane == 0) {
                float* dstp = (vec == 0) ? g_w_src[0] : (vec == 1) ? g_w_dst[0]
                             : (vec == 2) ? g_w_src[1] : g_w_dst[1];
                dstp[s] = sum;
            }
        }
    }
}

// =========================================================================
// K2: a_dst at self node (32g+31), warp per (branch, graph) (unchanged).
__global__ void dstval_kernel(const float* __restrict__ up_x,
                              const float* __restrict__ dn_x) {
    int wid = (blockIdx.x * blockDim.x + threadIdx.x) >> 5;
    int lane = threadIdx.x & 31;
    int branch = wid & 1, g = wid >> 1;
    const float* x = branch ? dn_x : up_x;
    float2 xv = *(const float2*)(x + (size_t)(g * 32 + 31) * SS + lane * 2);
    float2 wv = *(const float2*)(&g_w_dst[branch][lane * 2]);
    float s = xv.x * wv.x + xv.y * wv.y;
#pragma unroll
    for (int o = 16; o; o >>= 1) s += __shfl_xor_sync(0xffffffffu, s, o);
    if (lane == 0) g_a_dstv[branch][g] = s;
}

// =========================================================================
// K3: edge pass (unchanged, proven). Dual-edge ballot rounds.
__global__ void edge_kernel(const int* __restrict__ up_ei,
                            const int* __restrict__ dn_ei,
                            const float* __restrict__ up_x,
                            const float* __restrict__ dn_x) {
    int branch = blockIdx.y;
    const int*   ei = branch ? dn_ei : up_ei;
    const float* x  = branch ? dn_x  : up_x;
    float* acc   = g_acc[branch];
    float* denom = g_denom[branch];
    const float* adst = g_a_dstv[branch];
    int lane = threadIdx.x & 31;

    float4 wv = *(const float4*)&g_w_src[branch][(lane & 15) * 4];

    int e = blockIdx.x * blockDim.x + threadIdx.x;
    int d = ei[EE + e];                       // coalesced dst stream
    bool rel = (d & 31) == 31;
    int gph = d >> 5;
    int src = rel ? ei[e] : 0;                // lazy src load (~1/32 lanes)

    unsigned m = __ballot_sync(0xffffffffu, rel);
    while (m) {
        int lA = __ffs(m) - 1;  m &= m - 1;
        int lB = m ? (__ffs(m) - 1) : lA;
        bool two = (lB != lA);
        if (two) m &= m - 1;

        int myl = (lane < 16) ? lA : lB;
        int s2 = __shfl_sync(0xffffffffu, src, myl);
        int g2 = __shfl_sync(0xffffffffu, gph, myl);
        float ad = adst[g2];                                     // L2-resident
        float4 v = *(const float4*)(x + (size_t)s2 * SS + (lane & 15) * 4);
        float part = v.x * wv.x + v.y * wv.y + v.z * wv.z + v.w * wv.w;
#pragma unroll
        for (int o = 8; o; o >>= 1)
            part += __shfl_xor_sync(0xffffffffu, part, o);       // 16-group sum
        float ev = part + ad;
        ev = ev > 0.f ? ev : 0.2f * ev;                          // leaky_relu 0.2
        float p = __expf(ev);
        if (lane < 16 || two) {
            float* addr = acc + g2 * SS + (lane & 15) * 4;
            asm volatile("red.global.add.v4.f32 [%0], {%1,%2,%3,%4};"
                         :: "l"(addr), "f"(v.x * p), "f"(v.y * p),
                            "f"(v.z * p), "f"(v.w * p)
                         : "memory");
        }
        if (lane == 0) atomicAdd(denom + g2, p);
        if (lane == 16 && two) atomicAdd(denom + g2, p);
    }
}

// =========================================================================
// K4: epilogue, TWO graphs per warp (256 blocks x 8 warps x 2 = 4096).
// Per 2-row step: 4 independent LDG.128 (ulonglong2) + 2 LDS.128, then
// 16 FFMA2 into 8 independent chains. The 64KB Wt2 table read is amortized
// over 2 graphs (halves per-SM L1 wavefront demand vs R13).
// Lane owns cols {2l, 2l+1, 2l+64, 2l+65}.
__global__ void final_kernel(const float* __restrict__ upB,
                             const float* __restrict__ dnB,
                             const float* __restrict__ mlpW,
                             const float* __restrict__ mlpB,
                             float* __restrict__ out) {
    __shared__ __align__(16) ull vsh[8][2][SS];
    int t = threadIdx.x, w = t >> 5, lane = t & 31;
    int g0 = (blockIdx.x * 8 + w) * 2;

#pragma unroll
    for (int q = 0; q < 2; q++) {
        int g = g0 + q;
        float invu = __fdividef(1.f, g_denom[0][g] + 1e-16f);
        float invd = __fdividef(1.f, g_denom[1][g] + 1e-16f);
        int s0 = lane * 2;
        float2 au = *(const float2*)&g_acc[0][g * SS + s0];
        float2 ad = *(const float2*)&g_acc[1][g * SS + s0];
        ull p0, p1;
        asm("mov.b64 %0, {%1,%2};" : "=l"(p0) : "f"(au.x * invu), "f"(ad.x * invd));
        asm("mov.b64 %0, {%1,%2};" : "=l"(p1) : "f"(au.y * invu), "f"(ad.y * invd));
        vsh[w][q][s0]     = p0;
        vsh[w][q][s0 + 1] = p1;
    }
    __syncwarp();

    ull acc2[2][4] = {{0ull,0ull,0ull,0ull},{0ull,0ull,0ull,0ull}};
#pragma unroll 4
    for (int s = 0; s < SS; s += 2) {
        // batched independent loads first (MLP=6)
        const ulonglong2* r0 = (const ulonglong2*)&g_Wt2[s * HH];
        const ulonglong2* r1 = (const ulonglong2*)&g_Wt2[(s + 1) * HH];
        ulonglong2 w00 = r0[lane];        // cols 2l,2l+1   row s
        ulonglong2 w01 = r0[lane + 32];   // cols 2l+64,65  row s
        ulonglong2 w10 = r1[lane];        // row s+1
        ulonglong2 w11 = r1[lane + 32];
        ulonglong2 vA = *(const ulonglong2*)&vsh[w][0][s];   // v[s], v[s+1] graph A
        ulonglong2 vB = *(const ulonglong2*)&vsh[w][1][s];
#pragma unroll
        for (int q = 0; q < 2; q++) {
            ull v0 = q ? vB.x : vA.x;
            ull v1 = q ? vB.y : vA.y;
            asm("fma.rn.f32x2 %0, %1, %2, %0;" : "+l"(acc2[q][0]) : "l"(v0), "l"(w00.x));
            asm("fma.rn.f32x2 %0, %1, %2, %0;" : "+l"(acc2[q][1]) : "l"(v0), "l"(w00.y));
            asm("fma.rn.f32x2 %0, %1, %2, %0;" : "+l"(acc2[q][2]) : "l"(v0), "l"(w01.x));
            asm("fma.rn.f32x2 %0, %1, %2, %0;" : "+l"(acc2[q][3]) : "l"(v0), "l"(w01.y));
            asm("fma.rn.f32x2 %0, %1, %2, %0;" : "+l"(acc2[q][0]) : "l"(v1), "l"(w10.x));
            asm("fma.rn.f32x2 %0, %1, %2, %0;" : "+l"(acc2[q][1]) : "l"(v1), "l"(w10.y));
            asm("fma.rn.f32x2 %0, %1, %2, %0;" : "+l"(acc2[q][2]) : "l"(v1), "l"(w11.x));
            asm("fma.rn.f32x2 %0, %1, %2, %0;" : "+l"(acc2[q][3]) : "l"(v1), "l"(w11.y));
        }
    }

    int cols[4] = {2 * lane, 2 * lane + 1, 2 * lane + 64, 2 * lane + 65};
#pragma unroll
    for (int q = 0; q < 2; q++) {
        float pr = 0.f;
#pragma unroll
        for (int k = 0; k < 4; k++) {
            int c = cols[k];
            float su, sd;
            asm("mov.b64 {%0,%1}, %2;" : "=f"(su), "=f"(sd) : "l"(acc2[q][k]));
            float hu = 1.f / (1.f + __expf(-(su + upB[c])));
            float hd = 1.f / (1.f + __expf(-(sd + dnB[c])));
            pr += hu * hd * mlpW[c];
        }
#pragma unroll
        for (int o = 16; o; o >>= 1) pr += __shfl_xor_sync(0xffffffffu, pr, o);
        if (lane == 0) out[g0 + q] = pr + mlpB[0];
    }
}

// =========================================================================
extern "C" void kernel_launch(void* const* d_in, const int* in_sizes, int n_in,
                              void* d_out, int out_size) {
    const float* up_x  = (const float*)d_in[0];
    const int*   up_ei = (const int*)d_in[1];
    const float* dn_x  = (const float*)d_in[3];
    const int*   dn_ei = (const int*)d_in[4];
    const float* upW   = (const float*)d_in[6];
    const float* upAs  = (const float*)d_in[7];
    const float* upAd  = (const float*)d_in[8];
    const float* upB   = (const float*)d_in[9];
    const float* dnW   = (const float*)d_in[10];
    const float* dnAs  = (const float*)d_in[11];
    const float* dnAd  = (const float*)d_in[12];
    const float* dnB   = (const float*)d_in[13];
    const float* mlpW  = (const float*)d_in[14];
    const float* mlpB  = (const float*)d_in[15];
    float* out = (float*)d_out;

    init_kernel<<<152, 256>>>(upW, upAs, upAd, dnW, dnAs, dnAd);
    dstval_kernel<<<1024, 256>>>(up_x, dn_x);
    dim3 egrid(EE / 256, 2);
    edge_kernel<<<egrid, 256>>>(up_ei, dn_ei, up_x, dn_x);
    final_kernel<<<GG / 16, 256>>>(upB, dnB, mlpW, mlpB, out);
}